// round 7
// baseline (speedup 1.0000x reference)
#include <cuda_runtime.h>
#include <cuda_bf16.h>
#include <stdint.h>
#include <math.h>

#define E 8
#define D 1024
#define H 4096
#define O 1024
#define NTOK 4096

// ---------------- scratch ----------------
__device__ int   d_counts[E];
__device__ int   d_offs[E];
__device__ int   d_tok[E * NTOK];
__device__ float d_wt[E * NTOK];
__device__ int   d_slot[NTOK * 2];
__device__ float d_h[(size_t)2 * NTOK * H];   // gathered hidden, f32
__device__ float d_y[(size_t)2 * NTOK * O];   // gathered output, f32

// ---------------- helpers ----------------
__device__ __forceinline__ uint32_t smem_u32(const void* p) {
    uint32_t a;
    asm("{ .reg .u64 t; cvta.to.shared.u64 t, %1; cvt.u32.u64 %0, t; }" : "=r"(a) : "l"(p));
    return a;
}
__device__ __forceinline__ void ldm_x4(uint32_t* d, uint32_t a) {
    asm volatile("ldmatrix.sync.aligned.m8n8.x4.shared.b16 {%0,%1,%2,%3}, [%4];"
                 : "=r"(d[0]), "=r"(d[1]), "=r"(d[2]), "=r"(d[3]) : "r"(a));
}
__device__ __forceinline__ void mma16816(float* c, const uint32_t* a, const uint32_t* b) {
    asm volatile("mma.sync.aligned.m16n8k16.row.col.f32.bf16.bf16.f32 "
                 "{%0,%1,%2,%3}, {%4,%5,%6,%7}, {%8,%9}, {%0,%1,%2,%3};"
                 : "+f"(c[0]), "+f"(c[1]), "+f"(c[2]), "+f"(c[3])
                 : "r"(a[0]), "r"(a[1]), "r"(a[2]), "r"(a[3]), "r"(b[0]), "r"(b[1]));
}
__device__ __forceinline__ void split2(float x0, float x1, uint32_t& hi, uint32_t& lo) {
    __nv_bfloat16 h0 = __float2bfloat16(x0), h1 = __float2bfloat16(x1);
    float r0 = x0 - __bfloat162float(h0), r1 = x1 - __bfloat162float(h1);
    __nv_bfloat16 l0 = __float2bfloat16(r0), l1 = __float2bfloat16(r1);
    hi = ((uint32_t)__bfloat16_as_ushort(h1) << 16) | __bfloat16_as_ushort(h0);
    lo = ((uint32_t)__bfloat16_as_ushort(l1) << 16) | __bfloat16_as_ushort(l0);
}

// ---------------- routing ----------------
__global__ void zero_counts_kernel() {
    if (threadIdx.x < E) d_counts[threadIdx.x] = 0;
}

__global__ void gate_kernel(const float* __restrict__ x,
                            const float* __restrict__ Wg,
                            const float* __restrict__ bg) {
    int n = blockIdx.x;
    int tid = threadIdx.x;
    int w = tid >> 5;
    int lane = tid & 31;
    const float* xr = x + (size_t)n * D;

    float acc = 0.f;
    for (int d = lane; d < D; d += 32)
        acc += xr[d] * Wg[d * E + w];
    #pragma unroll
    for (int off = 16; off; off >>= 1)
        acc += __shfl_down_sync(0xffffffffu, acc, off);

    __shared__ float logits[E];
    if (lane == 0) logits[w] = acc + bg[w];
    __syncthreads();

    if (tid == 0) {
        int i0 = 0; float v0 = logits[0];
        #pragma unroll
        for (int e = 1; e < E; e++)
            if (logits[e] > v0) { v0 = logits[e]; i0 = e; }
        int i1 = -1; float v1 = -3.0e38f;
        #pragma unroll
        for (int e = 0; e < E; e++)
            if (e != i0 && logits[e] > v1) { v1 = logits[e]; i1 = e; }
        float w0 = 1.f / (1.f + expf(v1 - v0));
        float w1 = 1.f - w0;

        int p0 = atomicAdd(&d_counts[i0], 1);
        d_tok[i0 * NTOK + p0] = n;
        d_wt [i0 * NTOK + p0] = w0;
        d_slot[n * 2 + 0] = i0 * NTOK + p0;

        int p1 = atomicAdd(&d_counts[i1], 1);
        d_tok[i1 * NTOK + p1] = n;
        d_wt [i1 * NTOK + p1] = w1;
        d_slot[n * 2 + 1] = i1 * NTOK + p1;
    }
}

__global__ void scan_kernel() {
    if (threadIdx.x == 0) {
        int t = 0;
        #pragma unroll
        for (int e = 0; e < E; e++) { d_offs[e] = t; t += d_counts[e]; }
    }
}

// ---------------- HMMA grouped GEMM ----------------
// Block tile 192x128x32, 8 warps (4m x 2n), warp tile 64x64 wide-N for
// higher MAC/L1-byte. bf16x3 compensated, double-buffered dynamic SMEM,
// ldmatrix fragments, 80B row pitch (conflict-free).
#define MT 192
#define SROW 40
#define A_TILE (MT * SROW * 2)              // 15360
#define B_TILE (128 * SROW * 2)             // 10240
#define STAGE_BYTES (2 * A_TILE + 2 * B_TILE)  // 51200
#define OFF_AH 0
#define OFF_AL A_TILE
#define OFF_BH (2 * A_TILE)
#define OFF_BL (2 * A_TILE + B_TILE)

template <bool FIRST>
__global__ void __launch_bounds__(256)
gemm_hmma(const float* __restrict__ x, const float* __restrict__ W,
          const float* __restrict__ bias) {
    const int e = blockIdx.z;
    const int C = d_counts[e];
    const int m0 = blockIdx.y * MT;
    if (m0 >= C) return;
    const int n0 = blockIdx.x * 128;
    constexpr int K = FIRST ? D : H;
    constexpr int NOUT = FIRST ? H : O;
    const int base = d_offs[e];

    extern __shared__ __align__(16) char smem[];
    const uint32_t sb = smem_u32(smem);

    const int tid = threadIdx.x;
    const int lane = tid & 31;
    const int wid = tid >> 5;
    const int warp_m = wid >> 1;     // 0..3  (48 rows each)
    const int warp_n = wid & 1;      // 0..1  (64 cols each)
    const int g = lane >> 2;         // 0..7
    const int t = lane & 3;          // 0..3

    // B staging: k-quad kq (k=kq*4), n-quad nq (n=nq*4)
    const int kq = tid & 7;
    const int nq = tid >> 3;         // 0..31

    // A staging: threads 0..191 own one row each
    int mi = m0 + tid; if (mi > C - 1) mi = C - 1;
    const float* arow = FIRST ? (x + (size_t)d_tok[e * NTOK + mi] * D)
                              : (d_h + (size_t)(base + mi) * H);
    const float* wbase = W + (size_t)e * K * NOUT + (size_t)(kq * 4) * NOUT + n0 + nq * 4;

    float acc[3][8][4] = {};

    uint32_t pAh[16], pAl[16];
    float4 fb[4];

    auto gload = [&](int kb) {
        if (tid < MT) {
            const float* s = arow + kb;
            #pragma unroll
            for (int q = 0; q < 8; q++) {
                float4 f = *(const float4*)(s + q * 4);
                split2(f.x, f.y, pAh[2 * q], pAl[2 * q]);
                split2(f.z, f.w, pAh[2 * q + 1], pAl[2 * q + 1]);
            }
        }
        const float* wp = wbase + (size_t)kb * NOUT;
        #pragma unroll
        for (int r = 0; r < 4; r++)
            fb[r] = *(const float4*)(wp + (size_t)r * NOUT);
    };

    auto sstore = [&](int st) {
        char* sbp = smem + st * STAGE_BYTES;
        if (tid < MT) {
            __nv_bfloat16* pA_h = (__nv_bfloat16*)(sbp + OFF_AH) + tid * SROW;
            __nv_bfloat16* pA_l = (__nv_bfloat16*)(sbp + OFF_AL) + tid * SROW;
            #pragma unroll
            for (int q = 0; q < 4; q++) {
                *(uint4*)(pA_h + q * 8) = make_uint4(pAh[4*q], pAh[4*q+1], pAh[4*q+2], pAh[4*q+3]);
                *(uint4*)(pA_l + q * 8) = make_uint4(pAl[4*q], pAl[4*q+1], pAl[4*q+2], pAl[4*q+3]);
            }
        }
        __nv_bfloat16* pBh = (__nv_bfloat16*)(sbp + OFF_BH);
        __nv_bfloat16* pBl = (__nv_bfloat16*)(sbp + OFF_BL);
        float v[4][4] = {
            {fb[0].x, fb[0].y, fb[0].z, fb[0].w},
            {fb[1].x, fb[1].y, fb[1].z, fb[1].w},
            {fb[2].x, fb[2].y, fb[2].z, fb[2].w},
            {fb[3].x, fb[3].y, fb[3].z, fb[3].w}};
        #pragma unroll
        for (int j = 0; j < 4; j++) {   // n within quad
            uint32_t h0, l0, h1, l1;
            split2(v[0][j], v[1][j], h0, l0);   // k pair (0,1)
            split2(v[2][j], v[3][j], h1, l1);   // k pair (2,3)
            *(uint2*)(pBh + (nq * 4 + j) * SROW + kq * 4) = make_uint2(h0, h1);
            *(uint2*)(pBl + (nq * 4 + j) * SROW + kq * 4) = make_uint2(l0, l1);
        }
    };

    // ldmatrix lane offsets
    const uint32_t a_lane_off = (uint32_t)((lane & 15) * (SROW * 2) + (lane >> 4) * 16);
    const uint32_t b_lane_off = (uint32_t)(((lane & 7) + (lane >> 4) * 8) * (SROW * 2)
                                           + ((lane >> 3) & 1) * 16);

    auto compute = [&](int st) {
        uint32_t s0 = sb + (uint32_t)(st * STAGE_BYTES);
        uint32_t aAh = s0 + OFF_AH + a_lane_off + (uint32_t)(warp_m * 48 * SROW * 2);
        uint32_t aAl = s0 + OFF_AL + a_lane_off + (uint32_t)(warp_m * 48 * SROW * 2);
        uint32_t aBh = s0 + OFF_BH + b_lane_off + (uint32_t)(warp_n * 64 * SROW * 2);
        uint32_t aBl = s0 + OFF_BL + b_lane_off + (uint32_t)(warp_n * 64 * SROW * 2);
        #pragma unroll
        for (int kh = 0; kh < 2; kh++) {
            const uint32_t kb = kh * 32;
            uint32_t bh[4][4], bl[4][4];       // [pair of n-tiles][regs]
            #pragma unroll
            for (int p = 0; p < 4; p++) {
                ldm_x4(bh[p], aBh + kb + (uint32_t)(p * 16 * SROW * 2));
                ldm_x4(bl[p], aBl + kb + (uint32_t)(p * 16 * SROW * 2));
            }
            #pragma unroll
            for (int mt = 0; mt < 3; mt++) {
                uint32_t ah[4], al[4];
                ldm_x4(ah, aAh + kb + (uint32_t)(mt * 16 * SROW * 2));
                ldm_x4(al, aAl + kb + (uint32_t)(mt * 16 * SROW * 2));
                #pragma unroll
                for (int nt = 0; nt < 8; nt++) {
                    const uint32_t* bhf = &bh[nt >> 1][(nt & 1) * 2];
                    const uint32_t* blf = &bl[nt >> 1][(nt & 1) * 2];
                    mma16816(acc[mt][nt], ah, bhf);
                    mma16816(acc[mt][nt], al, bhf);
                    mma16816(acc[mt][nt], ah, blf);
                }
            }
        }
    };

    const int NCH = K / 32;
    gload(0);
    sstore(0);
    __syncthreads();
    for (int c = 0; c < NCH; c++) {
        if (c + 1 < NCH) gload((c + 1) * 32);
        compute(c & 1);
        if (c + 1 < NCH) sstore((c + 1) & 1);
        __syncthreads();
    }

    // ---------------- epilogue ----------------
    #pragma unroll
    for (int mt = 0; mt < 3; mt++) {
        const int rw = warp_m * 48 + mt * 16 + g;
        #pragma unroll
        for (int hrow = 0; hrow < 2; hrow++) {
            const int m = m0 + rw + hrow * 8;
            if (m >= C) continue;
            #pragma unroll
            for (int nt = 0; nt < 8; nt++) {
                const int col = n0 + warp_n * 64 + nt * 8 + 2 * t;
                float v0 = acc[mt][nt][hrow * 2 + 0] + bias[e * NOUT + col];
                float v1 = acc[mt][nt][hrow * 2 + 1] + bias[e * NOUT + col + 1];
                if (FIRST) {
                    float2 o;
                    o.x = fmaxf(v0, 0.f);
                    o.y = fmaxf(v1, 0.f);
                    *(float2*)(d_h + (size_t)(base + m) * H + col) = o;
                } else {
                    float wt = d_wt[e * NTOK + m];
                    float2 o;
                    o.x = wt * v0;
                    o.y = wt * v1;
                    *(float2*)(d_y + (size_t)(base + m) * O + col) = o;
                }
            }
        }
    }
}

// ---------------- combine ----------------
__global__ void combine_kernel(float* __restrict__ out) {
    int idx = blockIdx.x * blockDim.x + threadIdx.x;
    int n = idx / (O / 4);
    int o4 = (idx % (O / 4)) * 4;
    int s0 = d_slot[n * 2 + 0];
    int s1 = d_slot[n * 2 + 1];
    int c0 = d_offs[s0 >> 12] + (s0 & (NTOK - 1));
    int c1 = d_offs[s1 >> 12] + (s1 & (NTOK - 1));
    float4 a = *(const float4*)&d_y[(size_t)c0 * O + o4];
    float4 b = *(const float4*)&d_y[(size_t)c1 * O + o4];
    float4 r;
    r.x = a.x + b.x; r.y = a.y + b.y; r.z = a.z + b.z; r.w = a.w + b.w;
    *(float4*)&out[(size_t)n * O + o4] = r;
}

extern "C" void kernel_launch(void* const* d_in, const int* in_sizes, int n_in,
                              void* d_out, int out_size) {
    const float* x  = (const float*)d_in[0];
    const float* W1 = (const float*)d_in[1];
    const float* b1 = (const float*)d_in[2];
    const float* W2 = (const float*)d_in[3];
    const float* b2 = (const float*)d_in[4];
    const float* Wg = (const float*)d_in[5];
    const float* bg = (const float*)d_in[6];
    float* out = (float*)d_out;

    cudaFuncSetAttribute(gemm_hmma<true>,  cudaFuncAttributeMaxDynamicSharedMemorySize, 2 * STAGE_BYTES);
    cudaFuncSetAttribute(gemm_hmma<false>, cudaFuncAttributeMaxDynamicSharedMemorySize, 2 * STAGE_BYTES);

    zero_counts_kernel<<<1, 32>>>();
    gate_kernel<<<NTOK, 256>>>(x, Wg, bg);
    scan_kernel<<<1, 1>>>();

    const int MB = (NTOK + MT - 1) / MT;
    gemm_hmma<true ><<<dim3(H / 128, MB, E), 256, 2 * STAGE_BYTES>>>(x, W1, b1);
    gemm_hmma<false><<<dim3(O / 128, MB, E), 256, 2 * STAGE_BYTES>>>(nullptr, W2, b2);

    combine_kernel<<<(NTOK * O / 4) / 256, 256>>>(out);
}

// round 8
// speedup vs baseline: 1.0897x; 1.0897x over previous
#include <cuda_runtime.h>
#include <cuda_bf16.h>
#include <stdint.h>
#include <math.h>

#define E 8
#define D 1024
#define H 4096
#define O 1024
#define NTOK 4096

// ---------------- scratch ----------------
__device__ int   d_counts[E];
__device__ int   d_offs[E];
__device__ int   d_tok[E * NTOK];
__device__ float d_wt[E * NTOK];
__device__ int   d_slot[NTOK * 2];
__device__ float d_h[(size_t)2 * NTOK * H];   // gathered hidden, f32
__device__ float d_y[(size_t)2 * NTOK * O];   // gathered output, f32

// ---------------- helpers ----------------
__device__ __forceinline__ uint32_t smem_u32(const void* p) {
    uint32_t a;
    asm("{ .reg .u64 t; cvta.to.shared.u64 t, %1; cvt.u32.u64 %0, t; }" : "=r"(a) : "l"(p));
    return a;
}
__device__ __forceinline__ void ldm_x4(uint32_t* d, uint32_t a) {
    asm volatile("ldmatrix.sync.aligned.m8n8.x4.shared.b16 {%0,%1,%2,%3}, [%4];"
                 : "=r"(d[0]), "=r"(d[1]), "=r"(d[2]), "=r"(d[3]) : "r"(a));
}
// NOTE: non-volatile on purpose — pure register computation, lets ptxas schedule.
__device__ __forceinline__ void mma16816(float* c, const uint32_t* a, const uint32_t* b) {
    asm("mma.sync.aligned.m16n8k16.row.col.f32.bf16.bf16.f32 "
        "{%0,%1,%2,%3}, {%4,%5,%6,%7}, {%8,%9}, {%0,%1,%2,%3};"
        : "+f"(c[0]), "+f"(c[1]), "+f"(c[2]), "+f"(c[3])
        : "r"(a[0]), "r"(a[1]), "r"(a[2]), "r"(a[3]), "r"(b[0]), "r"(b[1]));
}
__device__ __forceinline__ void split2(float x0, float x1, uint32_t& hi, uint32_t& lo) {
    __nv_bfloat16 h0 = __float2bfloat16(x0), h1 = __float2bfloat16(x1);
    float r0 = x0 - __bfloat162float(h0), r1 = x1 - __bfloat162float(h1);
    __nv_bfloat16 l0 = __float2bfloat16(r0), l1 = __float2bfloat16(r1);
    hi = ((uint32_t)__bfloat16_as_ushort(h1) << 16) | __bfloat16_as_ushort(h0);
    lo = ((uint32_t)__bfloat16_as_ushort(l1) << 16) | __bfloat16_as_ushort(l0);
}

// ---------------- routing ----------------
__global__ void zero_counts_kernel() {
    if (threadIdx.x < E) d_counts[threadIdx.x] = 0;
}

__global__ void gate_kernel(const float* __restrict__ x,
                            const float* __restrict__ Wg,
                            const float* __restrict__ bg) {
    int n = blockIdx.x;
    int tid = threadIdx.x;
    int w = tid >> 5;
    int lane = tid & 31;
    const float* xr = x + (size_t)n * D;

    float acc = 0.f;
    for (int d = lane; d < D; d += 32)
        acc += xr[d] * Wg[d * E + w];
    #pragma unroll
    for (int off = 16; off; off >>= 1)
        acc += __shfl_down_sync(0xffffffffu, acc, off);

    __shared__ float logits[E];
    if (lane == 0) logits[w] = acc + bg[w];
    __syncthreads();

    if (tid == 0) {
        int i0 = 0; float v0 = logits[0];
        #pragma unroll
        for (int e = 1; e < E; e++)
            if (logits[e] > v0) { v0 = logits[e]; i0 = e; }
        int i1 = -1; float v1 = -3.0e38f;
        #pragma unroll
        for (int e = 0; e < E; e++)
            if (e != i0 && logits[e] > v1) { v1 = logits[e]; i1 = e; }
        float w0 = 1.f / (1.f + expf(v1 - v0));
        float w1 = 1.f - w0;

        int p0 = atomicAdd(&d_counts[i0], 1);
        d_tok[i0 * NTOK + p0] = n;
        d_wt [i0 * NTOK + p0] = w0;
        d_slot[n * 2 + 0] = i0 * NTOK + p0;

        int p1 = atomicAdd(&d_counts[i1], 1);
        d_tok[i1 * NTOK + p1] = n;
        d_wt [i1 * NTOK + p1] = w1;
        d_slot[n * 2 + 1] = i1 * NTOK + p1;
    }
}

__global__ void scan_kernel() {
    if (threadIdx.x == 0) {
        int t = 0;
        #pragma unroll
        for (int e = 0; e < E; e++) { d_offs[e] = t; t += d_counts[e]; }
    }
}

// ---------------- HMMA grouped GEMM ----------------
// Block tile 128x128x32, 8 warps (2m x 4n), warp tile 64x32, bf16x3 compensated.
// Double-buffered dynamic SMEM, ldmatrix fragment loads, one sync per chunk.
// Compute loop issues 3 separated passes (hh, lh, hl) so same-accumulator MMAs
// are 16 independent instructions apart (breaks the serial latency chain).
#define SROW 40
#define TILE_BYTES (128 * SROW * 2)          // 10240
#define STAGE_BYTES (4 * TILE_BYTES)         // Ah|Al|Bh|Bl = 40960
#define OFF_AH 0
#define OFF_AL TILE_BYTES
#define OFF_BH (2 * TILE_BYTES)
#define OFF_BL (3 * TILE_BYTES)

template <bool FIRST>
__global__ void __launch_bounds__(256)
gemm_hmma(const float* __restrict__ x, const float* __restrict__ W,
          const float* __restrict__ bias) {
    const int e = blockIdx.z;
    const int C = d_counts[e];
    const int m0 = blockIdx.y * 128;
    if (m0 >= C) return;
    const int n0 = blockIdx.x * 128;
    constexpr int K = FIRST ? D : H;
    constexpr int NOUT = FIRST ? H : O;
    const int base = d_offs[e];

    extern __shared__ __align__(16) char smem[];
    const uint32_t sb = smem_u32(smem);

    const int tid = threadIdx.x;
    const int lane = tid & 31;
    const int wid = tid >> 5;
    const int warp_m = wid >> 2;     // 0..1
    const int warp_n = wid & 3;      // 0..3
    const int g = lane >> 2;         // 0..7
    const int t = lane & 3;          // 0..3

    // A staging: row lr, k-half hf (16 of 32)
    const int lr = tid >> 1;
    const int hf = tid & 1;
    // B staging: k-quad kq (k=kq*4), n-quad nq (n=nq*4)
    const int kq = tid & 7;
    const int nq = tid >> 3;         // 0..31

    int mi = m0 + lr; if (mi > C - 1) mi = C - 1;
    const float* arow = FIRST ? (x + (size_t)d_tok[e * NTOK + mi] * D)
                              : (d_h + (size_t)(base + mi) * H);
    const float* wbase = W + (size_t)e * K * NOUT + (size_t)(kq * 4) * NOUT + n0 + nq * 4;

    float acc[4][4][4] = {};

    uint4 rAh0, rAh1, rAl0, rAl1;
    float4 fb[4];

    auto gload = [&](int kb) {
        const float* s = arow + kb + hf * 16;
        float4 f0 = *(const float4*)(s);
        float4 f1 = *(const float4*)(s + 4);
        float4 f2 = *(const float4*)(s + 8);
        float4 f3 = *(const float4*)(s + 12);
        uint32_t h[8], l[8];
        split2(f0.x, f0.y, h[0], l[0]); split2(f0.z, f0.w, h[1], l[1]);
        split2(f1.x, f1.y, h[2], l[2]); split2(f1.z, f1.w, h[3], l[3]);
        split2(f2.x, f2.y, h[4], l[4]); split2(f2.z, f2.w, h[5], l[5]);
        split2(f3.x, f3.y, h[6], l[6]); split2(f3.z, f3.w, h[7], l[7]);
        rAh0 = make_uint4(h[0], h[1], h[2], h[3]);
        rAh1 = make_uint4(h[4], h[5], h[6], h[7]);
        rAl0 = make_uint4(l[0], l[1], l[2], l[3]);
        rAl1 = make_uint4(l[4], l[5], l[6], l[7]);
        const float* wp = wbase + (size_t)kb * NOUT;
        #pragma unroll
        for (int r = 0; r < 4; r++)
            fb[r] = *(const float4*)(wp + (size_t)r * NOUT);
    };

    auto sstore = [&](int st) {
        char* sbp = smem + st * STAGE_BYTES;
        __nv_bfloat16* pAh = (__nv_bfloat16*)(sbp + OFF_AH);
        __nv_bfloat16* pAl = (__nv_bfloat16*)(sbp + OFF_AL);
        __nv_bfloat16* pBh = (__nv_bfloat16*)(sbp + OFF_BH);
        __nv_bfloat16* pBl = (__nv_bfloat16*)(sbp + OFF_BL);
        *(uint4*)(pAh + lr * SROW + hf * 16)     = rAh0;
        *(uint4*)(pAh + lr * SROW + hf * 16 + 8) = rAh1;
        *(uint4*)(pAl + lr * SROW + hf * 16)     = rAl0;
        *(uint4*)(pAl + lr * SROW + hf * 16 + 8) = rAl1;
        float v[4][4] = {
            {fb[0].x, fb[0].y, fb[0].z, fb[0].w},
            {fb[1].x, fb[1].y, fb[1].z, fb[1].w},
            {fb[2].x, fb[2].y, fb[2].z, fb[2].w},
            {fb[3].x, fb[3].y, fb[3].z, fb[3].w}};
        #pragma unroll
        for (int j = 0; j < 4; j++) {   // n within quad
            uint32_t h0, l0, h1, l1;
            split2(v[0][j], v[1][j], h0, l0);   // k pair (0,1)
            split2(v[2][j], v[3][j], h1, l1);   // k pair (2,3)
            *(uint2*)(pBh + (nq * 4 + j) * SROW + kq * 4) = make_uint2(h0, h1);
            *(uint2*)(pBl + (nq * 4 + j) * SROW + kq * 4) = make_uint2(l0, l1);
        }
    };

    // ldmatrix addressing
    const uint32_t a_lane_off = (uint32_t)((lane & 15) * (SROW * 2) + (lane >> 4) * 16);
    const uint32_t b_lane_off = (uint32_t)(((lane & 7) + (lane >> 4) * 8) * (SROW * 2)
                                           + ((lane >> 3) & 1) * 16);

    auto compute = [&](int st) {
        uint32_t s0 = sb + (uint32_t)(st * STAGE_BYTES);
        uint32_t aAh = s0 + OFF_AH + a_lane_off + (uint32_t)(warp_m * 64 * SROW * 2);
        uint32_t aAl = s0 + OFF_AL + a_lane_off + (uint32_t)(warp_m * 64 * SROW * 2);
        uint32_t aBh = s0 + OFF_BH + b_lane_off + (uint32_t)(warp_n * 32 * SROW * 2);
        uint32_t aBl = s0 + OFF_BL + b_lane_off + (uint32_t)(warp_n * 32 * SROW * 2);
        #pragma unroll
        for (int kh = 0; kh < 2; kh++) {
            const uint32_t kb = kh * 32;
            uint32_t bh[2][4], bl[2][4];       // [pair][4 regs = 2 n-tiles]
            uint32_t ah[4][4], al[4][4];
            #pragma unroll
            for (int p = 0; p < 2; p++) {
                ldm_x4(bh[p], aBh + kb + (uint32_t)(p * 16 * SROW * 2));
                ldm_x4(bl[p], aBl + kb + (uint32_t)(p * 16 * SROW * 2));
            }
            #pragma unroll
            for (int mt = 0; mt < 4; mt++) {
                ldm_x4(ah[mt], aAh + kb + (uint32_t)(mt * 16 * SROW * 2));
                ldm_x4(al[mt], aAl + kb + (uint32_t)(mt * 16 * SROW * 2));
            }
            // pass 1: Ah * Bh  (16 independent MMAs)
            #pragma unroll
            for (int mt = 0; mt < 4; mt++)
                #pragma unroll
                for (int nt = 0; nt < 4; nt++)
                    mma16816(acc[mt][nt], ah[mt], &bh[nt >> 1][(nt & 1) * 2]);
            // pass 2: Al * Bh
            #pragma unroll
            for (int mt = 0; mt < 4; mt++)
                #pragma unroll
                for (int nt = 0; nt < 4; nt++)
                    mma16816(acc[mt][nt], al[mt], &bh[nt >> 1][(nt & 1) * 2]);
            // pass 3: Ah * Bl
            #pragma unroll
            for (int mt = 0; mt < 4; mt++)
                #pragma unroll
                for (int nt = 0; nt < 4; nt++)
                    mma16816(acc[mt][nt], ah[mt], &bl[nt >> 1][(nt & 1) * 2]);
        }
    };

    const int NCH = K / 32;
    gload(0);
    sstore(0);
    __syncthreads();
    for (int c = 0; c < NCH; c++) {
        if (c + 1 < NCH) gload((c + 1) * 32);
        compute(c & 1);
        if (c + 1 < NCH) sstore((c + 1) & 1);
        __syncthreads();
    }

    // ---------------- epilogue ----------------
    #pragma unroll
    for (int mt = 0; mt < 4; mt++) {
        const int rw = warp_m * 64 + mt * 16 + g;
        #pragma unroll
        for (int hrow = 0; hrow < 2; hrow++) {
            const int m = m0 + rw + hrow * 8;
            if (m >= C) continue;
            #pragma unroll
            for (int nt = 0; nt < 4; nt++) {
                const int col = n0 + warp_n * 32 + nt * 8 + 2 * t;
                float v0 = acc[mt][nt][hrow * 2 + 0] + bias[e * NOUT + col];
                float v1 = acc[mt][nt][hrow * 2 + 1] + bias[e * NOUT + col + 1];
                if (FIRST) {
                    float2 o;
                    o.x = fmaxf(v0, 0.f);
                    o.y = fmaxf(v1, 0.f);
                    *(float2*)(d_h + (size_t)(base + m) * H + col) = o;
                } else {
                    float wt = d_wt[e * NTOK + m];
                    float2 o;
                    o.x = wt * v0;
                    o.y = wt * v1;
                    *(float2*)(d_y + (size_t)(base + m) * O + col) = o;
                }
            }
        }
    }
}

// ---------------- combine ----------------
__global__ void combine_kernel(float* __restrict__ out) {
    int idx = blockIdx.x * blockDim.x + threadIdx.x;
    int n = idx / (O / 4);
    int o4 = (idx % (O / 4)) * 4;
    int s0 = d_slot[n * 2 + 0];
    int s1 = d_slot[n * 2 + 1];
    int c0 = d_offs[s0 >> 12] + (s0 & (NTOK - 1));
    int c1 = d_offs[s1 >> 12] + (s1 & (NTOK - 1));
    float4 a = *(const float4*)&d_y[(size_t)c0 * O + o4];
    float4 b = *(const float4*)&d_y[(size_t)c1 * O + o4];
    float4 r;
    r.x = a.x + b.x; r.y = a.y + b.y; r.z = a.z + b.z; r.w = a.w + b.w;
    *(float4*)&out[(size_t)n * O + o4] = r;
}

extern "C" void kernel_launch(void* const* d_in, const int* in_sizes, int n_in,
                              void* d_out, int out_size) {
    const float* x  = (const float*)d_in[0];
    const float* W1 = (const float*)d_in[1];
    const float* b1 = (const float*)d_in[2];
    const float* W2 = (const float*)d_in[3];
    const float* b2 = (const float*)d_in[4];
    const float* Wg = (const float*)d_in[5];
    const float* bg = (const float*)d_in[6];
    float* out = (float*)d_out;

    cudaFuncSetAttribute(gemm_hmma<true>,  cudaFuncAttributeMaxDynamicSharedMemorySize, 2 * STAGE_BYTES);
    cudaFuncSetAttribute(gemm_hmma<false>, cudaFuncAttributeMaxDynamicSharedMemorySize, 2 * STAGE_BYTES);

    zero_counts_kernel<<<1, 32>>>();
    gate_kernel<<<NTOK, 256>>>(x, Wg, bg);
    scan_kernel<<<1, 1>>>();

    gemm_hmma<true ><<<dim3(H / 128, NTOK / 128, E), 256, 2 * STAGE_BYTES>>>(x, W1, b1);
    gemm_hmma<false><<<dim3(O / 128, NTOK / 128, E), 256, 2 * STAGE_BYTES>>>(nullptr, W2, b2);

    combine_kernel<<<(NTOK * O / 4) / 256, 256>>>(out);
}

// round 9
// speedup vs baseline: 1.3532x; 1.2418x over previous
#include <cuda_runtime.h>
#include <cuda_bf16.h>
#include <stdint.h>
#include <math.h>

#define E 8
#define D 1024
#define H 4096
#define O 1024
#define NTOK 4096

// ---------------- scratch ----------------
__device__ int   d_counts[E];
__device__ int   d_offs[E];
__device__ int   d_tok[E * NTOK];
__device__ float d_wt[E * NTOK];
__device__ int   d_slot[NTOK * 2];
__device__ float d_h[(size_t)2 * NTOK * H];   // gathered hidden, f32
__device__ float d_y[(size_t)2 * NTOK * O];   // gathered output, f32

// ---------------- helpers ----------------
__device__ __forceinline__ uint32_t smem_u32(const void* p) {
    uint32_t a;
    asm("{ .reg .u64 t; cvta.to.shared.u64 t, %1; cvt.u32.u64 %0, t; }" : "=r"(a) : "l"(p));
    return a;
}
__device__ __forceinline__ void ldm_x4(uint32_t* d, uint32_t a) {
    asm volatile("ldmatrix.sync.aligned.m8n8.x4.shared.b16 {%0,%1,%2,%3}, [%4];"
                 : "=r"(d[0]), "=r"(d[1]), "=r"(d[2]), "=r"(d[3]) : "r"(a));
}
// non-volatile: pure register computation, lets ptxas schedule.
__device__ __forceinline__ void mma16816(float* c, const uint32_t* a, const uint32_t* b) {
    asm("mma.sync.aligned.m16n8k16.row.col.f32.bf16.bf16.f32 "
        "{%0,%1,%2,%3}, {%4,%5,%6,%7}, {%8,%9}, {%0,%1,%2,%3};"
        : "+f"(c[0]), "+f"(c[1]), "+f"(c[2]), "+f"(c[3])
        : "r"(a[0]), "r"(a[1]), "r"(a[2]), "r"(a[3]), "r"(b[0]), "r"(b[1]));
}
__device__ __forceinline__ void split2(float x0, float x1, uint32_t& hi, uint32_t& lo) {
    __nv_bfloat16 h0 = __float2bfloat16(x0), h1 = __float2bfloat16(x1);
    float r0 = x0 - __bfloat162float(h0), r1 = x1 - __bfloat162float(h1);
    __nv_bfloat16 l0 = __float2bfloat16(r0), l1 = __float2bfloat16(r1);
    hi = ((uint32_t)__bfloat16_as_ushort(h1) << 16) | __bfloat16_as_ushort(h0);
    lo = ((uint32_t)__bfloat16_as_ushort(l1) << 16) | __bfloat16_as_ushort(l0);
}

// ---------------- routing ----------------
__global__ void zero_counts_kernel() {
    if (threadIdx.x < E) d_counts[threadIdx.x] = 0;
}

__global__ void gate_kernel(const float* __restrict__ x,
                            const float* __restrict__ Wg,
                            const float* __restrict__ bg) {
    int n = blockIdx.x;
    int tid = threadIdx.x;
    int w = tid >> 5;
    int lane = tid & 31;
    const float* xr = x + (size_t)n * D;

    float acc = 0.f;
    for (int d = lane; d < D; d += 32)
        acc += xr[d] * Wg[d * E + w];
    #pragma unroll
    for (int off = 16; off; off >>= 1)
        acc += __shfl_down_sync(0xffffffffu, acc, off);

    __shared__ float logits[E];
    if (lane == 0) logits[w] = acc + bg[w];
    __syncthreads();

    if (tid == 0) {
        int i0 = 0; float v0 = logits[0];
        #pragma unroll
        for (int e = 1; e < E; e++)
            if (logits[e] > v0) { v0 = logits[e]; i0 = e; }
        int i1 = -1; float v1 = -3.0e38f;
        #pragma unroll
        for (int e = 0; e < E; e++)
            if (e != i0 && logits[e] > v1) { v1 = logits[e]; i1 = e; }
        float w0 = 1.f / (1.f + expf(v1 - v0));
        float w1 = 1.f - w0;

        int p0 = atomicAdd(&d_counts[i0], 1);
        d_tok[i0 * NTOK + p0] = n;
        d_wt [i0 * NTOK + p0] = w0;
        d_slot[n * 2 + 0] = i0 * NTOK + p0;

        int p1 = atomicAdd(&d_counts[i1], 1);
        d_tok[i1 * NTOK + p1] = n;
        d_wt [i1 * NTOK + p1] = w1;
        d_slot[n * 2 + 1] = i1 * NTOK + p1;
    }
}

__global__ void scan_kernel() {
    if (threadIdx.x == 0) {
        int t = 0;
        #pragma unroll
        for (int e = 0; e < E; e++) { d_offs[e] = t; t += d_counts[e]; }
    }
}

// ---------------- HMMA grouped GEMM ----------------
// Block tile 128x128x32, 8 warps (2m x 4n), warp tile 64x32, bf16x3 compensated.
// Single-stage static SMEM (40KB) -> 2 CTAs/SM. No register prefetch: the
// co-resident CTA hides this CTA's LDG/barrier gaps. <=128 regs enforced.
#define SROW 40
#define TILE_BYTES (128 * SROW * 2)          // 10240

template <bool FIRST>
__global__ void __launch_bounds__(256, 2)
gemm_hmma(const float* __restrict__ x, const float* __restrict__ W,
          const float* __restrict__ bias) {
    const int e = blockIdx.z;
    const int C = d_counts[e];
    const int m0 = blockIdx.y * 128;
    if (m0 >= C) return;
    const int n0 = blockIdx.x * 128;
    constexpr int K = FIRST ? D : H;
    constexpr int NOUT = FIRST ? H : O;
    const int base = d_offs[e];

    __shared__ __align__(16) __nv_bfloat16 sAh[128][SROW];
    __shared__ __align__(16) __nv_bfloat16 sAl[128][SROW];
    __shared__ __align__(16) __nv_bfloat16 sBh[128][SROW];
    __shared__ __align__(16) __nv_bfloat16 sBl[128][SROW];

    const int tid = threadIdx.x;
    const int lane = tid & 31;
    const int wid = tid >> 5;
    const int warp_m = wid >> 2;     // 0..1
    const int warp_n = wid & 3;      // 0..3

    // A staging: row lr, k-half hf (16 of 32)
    const int lr = tid >> 1;
    const int hf = tid & 1;
    // B staging: k-quad kq (k=kq*4), n-quad nq (n=nq*4)
    const int kq = tid & 7;
    const int nq = tid >> 3;         // 0..31

    int mi = m0 + lr; if (mi > C - 1) mi = C - 1;
    const float* arow = FIRST ? (x + (size_t)d_tok[e * NTOK + mi] * D)
                              : (d_h + (size_t)(base + mi) * H);
    const float* wbase = W + (size_t)e * K * NOUT + (size_t)(kq * 4) * NOUT + n0 + nq * 4;

    float acc[4][4][4] = {};

    // stage one K-chunk: load global -> split -> smem (no long-lived regs)
    auto stage = [&](int kb) {
        {
            const float* s = arow + kb + hf * 16;
            float4 f0 = *(const float4*)(s);
            float4 f1 = *(const float4*)(s + 4);
            float4 f2 = *(const float4*)(s + 8);
            float4 f3 = *(const float4*)(s + 12);
            uint32_t h[8], l[8];
            split2(f0.x, f0.y, h[0], l[0]); split2(f0.z, f0.w, h[1], l[1]);
            split2(f1.x, f1.y, h[2], l[2]); split2(f1.z, f1.w, h[3], l[3]);
            split2(f2.x, f2.y, h[4], l[4]); split2(f2.z, f2.w, h[5], l[5]);
            split2(f3.x, f3.y, h[6], l[6]); split2(f3.z, f3.w, h[7], l[7]);
            *(uint4*)&sAh[lr][hf * 16]     = make_uint4(h[0], h[1], h[2], h[3]);
            *(uint4*)&sAh[lr][hf * 16 + 8] = make_uint4(h[4], h[5], h[6], h[7]);
            *(uint4*)&sAl[lr][hf * 16]     = make_uint4(l[0], l[1], l[2], l[3]);
            *(uint4*)&sAl[lr][hf * 16 + 8] = make_uint4(l[4], l[5], l[6], l[7]);
        }
        {
            const float* wp = wbase + (size_t)kb * NOUT;
            float4 r0 = *(const float4*)(wp);
            float4 r1 = *(const float4*)(wp + (size_t)NOUT);
            float4 r2 = *(const float4*)(wp + (size_t)2 * NOUT);
            float4 r3 = *(const float4*)(wp + (size_t)3 * NOUT);
            float v[4][4] = {
                {r0.x, r0.y, r0.z, r0.w},
                {r1.x, r1.y, r1.z, r1.w},
                {r2.x, r2.y, r2.z, r2.w},
                {r3.x, r3.y, r3.z, r3.w}};
            #pragma unroll
            for (int j = 0; j < 4; j++) {   // n within quad
                uint32_t h0, l0, h1, l1;
                split2(v[0][j], v[1][j], h0, l0);   // k pair (0,1)
                split2(v[2][j], v[3][j], h1, l1);   // k pair (2,3)
                *(uint2*)&sBh[nq * 4 + j][kq * 4] = make_uint2(h0, h1);
                *(uint2*)&sBl[nq * 4 + j][kq * 4] = make_uint2(l0, l1);
            }
        }
    };

    // ldmatrix addressing
    const uint32_t sb_Ah = smem_u32(&sAh[0][0]);
    const uint32_t sb_Al = smem_u32(&sAl[0][0]);
    const uint32_t sb_Bh = smem_u32(&sBh[0][0]);
    const uint32_t sb_Bl = smem_u32(&sBl[0][0]);
    const uint32_t a_lane_off = (uint32_t)((lane & 15) * (SROW * 2) + (lane >> 4) * 16)
                              + (uint32_t)(warp_m * 64 * SROW * 2);
    const uint32_t b_lane_off = (uint32_t)(((lane & 7) + (lane >> 4) * 8) * (SROW * 2)
                                           + ((lane >> 3) & 1) * 16)
                              + (uint32_t)(warp_n * 32 * SROW * 2);

    auto compute = [&]() {
        #pragma unroll
        for (int kh = 0; kh < 2; kh++) {
            const uint32_t kb = kh * 32;
            uint32_t bh[2][4], bl[2][4];
            uint32_t ah[4][4], al[4][4];
            #pragma unroll
            for (int p = 0; p < 2; p++) {
                ldm_x4(bh[p], sb_Bh + b_lane_off + kb + (uint32_t)(p * 16 * SROW * 2));
                ldm_x4(bl[p], sb_Bl + b_lane_off + kb + (uint32_t)(p * 16 * SROW * 2));
            }
            #pragma unroll
            for (int mt = 0; mt < 4; mt++) {
                ldm_x4(ah[mt], sb_Ah + a_lane_off + kb + (uint32_t)(mt * 16 * SROW * 2));
                ldm_x4(al[mt], sb_Al + a_lane_off + kb + (uint32_t)(mt * 16 * SROW * 2));
            }
            #pragma unroll
            for (int mt = 0; mt < 4; mt++)
                #pragma unroll
                for (int nt = 0; nt < 4; nt++)
                    mma16816(acc[mt][nt], ah[mt], &bh[nt >> 1][(nt & 1) * 2]);
            #pragma unroll
            for (int mt = 0; mt < 4; mt++)
                #pragma unroll
                for (int nt = 0; nt < 4; nt++)
                    mma16816(acc[mt][nt], al[mt], &bh[nt >> 1][(nt & 1) * 2]);
            #pragma unroll
            for (int mt = 0; mt < 4; mt++)
                #pragma unroll
                for (int nt = 0; nt < 4; nt++)
                    mma16816(acc[mt][nt], ah[mt], &bl[nt >> 1][(nt & 1) * 2]);
        }
    };

    const int NCH = K / 32;
    for (int c = 0; c < NCH; c++) {
        stage(c * 32);
        __syncthreads();
        compute();
        __syncthreads();
    }

    // ---------------- epilogue ----------------
    const int g = lane >> 2;
    const int t = lane & 3;
    #pragma unroll
    for (int mt = 0; mt < 4; mt++) {
        const int rw = warp_m * 64 + mt * 16 + g;
        #pragma unroll
        for (int hrow = 0; hrow < 2; hrow++) {
            const int m = m0 + rw + hrow * 8;
            if (m >= C) continue;
            #pragma unroll
            for (int nt = 0; nt < 4; nt++) {
                const int col = n0 + warp_n * 32 + nt * 8 + 2 * t;
                float v0 = acc[mt][nt][hrow * 2 + 0] + bias[e * NOUT + col];
                float v1 = acc[mt][nt][hrow * 2 + 1] + bias[e * NOUT + col + 1];
                if (FIRST) {
                    float2 o;
                    o.x = fmaxf(v0, 0.f);
                    o.y = fmaxf(v1, 0.f);
                    *(float2*)(d_h + (size_t)(base + m) * H + col) = o;
                } else {
                    float wt = d_wt[e * NTOK + m];
                    float2 o;
                    o.x = wt * v0;
                    o.y = wt * v1;
                    *(float2*)(d_y + (size_t)(base + m) * O + col) = o;
                }
            }
        }
    }
}

// ---------------- combine ----------------
__global__ void combine_kernel(float* __restrict__ out) {
    int idx = blockIdx.x * blockDim.x + threadIdx.x;
    int n = idx / (O / 4);
    int o4 = (idx % (O / 4)) * 4;
    int s0 = d_slot[n * 2 + 0];
    int s1 = d_slot[n * 2 + 1];
    int c0 = d_offs[s0 >> 12] + (s0 & (NTOK - 1));
    int c1 = d_offs[s1 >> 12] + (s1 & (NTOK - 1));
    float4 a = *(const float4*)&d_y[(size_t)c0 * O + o4];
    float4 b = *(const float4*)&d_y[(size_t)c1 * O + o4];
    float4 r;
    r.x = a.x + b.x; r.y = a.y + b.y; r.z = a.z + b.z; r.w = a.w + b.w;
    *(float4*)&out[(size_t)n * O + o4] = r;
}

extern "C" void kernel_launch(void* const* d_in, const int* in_sizes, int n_in,
                              void* d_out, int out_size) {
    const float* x  = (const float*)d_in[0];
    const float* W1 = (const float*)d_in[1];
    const float* b1 = (const float*)d_in[2];
    const float* W2 = (const float*)d_in[3];
    const float* b2 = (const float*)d_in[4];
    const float* Wg = (const float*)d_in[5];
    const float* bg = (const float*)d_in[6];
    float* out = (float*)d_out;

    zero_counts_kernel<<<1, 32>>>();
    gate_kernel<<<NTOK, 256>>>(x, Wg, bg);
    scan_kernel<<<1, 1>>>();

    gemm_hmma<true ><<<dim3(H / 128, NTOK / 128, E), 256>>>(x, W1, b1);
    gemm_hmma<false><<<dim3(O / 128, NTOK / 128, E), 256>>>(nullptr, W2, b2);

    combine_kernel<<<(NTOK * O / 4) / 256, 256>>>(out);
}

// round 10
// speedup vs baseline: 1.6531x; 1.2216x over previous
#include <cuda_runtime.h>
#include <cuda_fp16.h>
#include <stdint.h>
#include <math.h>

#define E 8
#define D 1024
#define H 4096
#define O 1024
#define NTOK 4096

// ---------------- scratch ----------------
__device__ int   d_counts[E];
__device__ int   d_offs[E];
__device__ int   d_tok[E * NTOK];
__device__ float d_wt[E * NTOK];
__device__ int   d_slot[NTOK * 2];
__device__ float d_h[(size_t)2 * NTOK * H];   // gathered hidden, f32
__device__ float d_y[(size_t)2 * NTOK * O];   // gathered output, f32

// ---------------- helpers ----------------
__device__ __forceinline__ uint32_t smem_u32(const void* p) {
    uint32_t a;
    asm("{ .reg .u64 t; cvta.to.shared.u64 t, %1; cvt.u32.u64 %0, t; }" : "=r"(a) : "l"(p));
    return a;
}
__device__ __forceinline__ void ldm_x4(uint32_t* d, uint32_t a) {
    asm volatile("ldmatrix.sync.aligned.m8n8.x4.shared.b16 {%0,%1,%2,%3}, [%4];"
                 : "=r"(d[0]), "=r"(d[1]), "=r"(d[2]), "=r"(d[3]) : "r"(a));
}
// non-volatile: pure register computation, lets ptxas schedule.
__device__ __forceinline__ void mma16816(float* c, const uint32_t* a, const uint32_t* b) {
    asm("mma.sync.aligned.m16n8k16.row.col.f32.f16.f16.f32 "
        "{%0,%1,%2,%3}, {%4,%5,%6,%7}, {%8,%9}, {%0,%1,%2,%3};"
        : "+f"(c[0]), "+f"(c[1]), "+f"(c[2]), "+f"(c[3])
        : "r"(a[0]), "r"(a[1]), "r"(a[2]), "r"(a[3]), "r"(b[0]), "r"(b[1]));
}
// fp16 hi/lo split of two floats, packed as half2 words
__device__ __forceinline__ void split2h(float x0, float x1, uint32_t& hi, uint32_t& lo) {
    __half h0 = __float2half_rn(x0), h1 = __float2half_rn(x1);
    __half l0 = __float2half_rn(x0 - __half2float(h0));
    __half l1 = __float2half_rn(x1 - __half2float(h1));
    hi = ((uint32_t)__half_as_ushort(h1) << 16) | __half_as_ushort(h0);
    lo = ((uint32_t)__half_as_ushort(l1) << 16) | __half_as_ushort(l0);
}
__device__ __forceinline__ uint32_t pack2h(float x0, float x1) {
    return ((uint32_t)__half_as_ushort(__float2half_rn(x1)) << 16)
         | __half_as_ushort(__float2half_rn(x0));
}

// ---------------- routing ----------------
__global__ void zero_counts_kernel() {
    if (threadIdx.x < E) d_counts[threadIdx.x] = 0;
}

__global__ void gate_kernel(const float* __restrict__ x,
                            const float* __restrict__ Wg,
                            const float* __restrict__ bg) {
    int n = blockIdx.x;
    int tid = threadIdx.x;
    int w = tid >> 5;
    int lane = tid & 31;
    const float* xr = x + (size_t)n * D;

    float acc = 0.f;
    for (int d = lane; d < D; d += 32)
        acc += xr[d] * Wg[d * E + w];
    #pragma unroll
    for (int off = 16; off; off >>= 1)
        acc += __shfl_down_sync(0xffffffffu, acc, off);

    __shared__ float logits[E];
    if (lane == 0) logits[w] = acc + bg[w];
    __syncthreads();

    if (tid == 0) {
        int i0 = 0; float v0 = logits[0];
        #pragma unroll
        for (int e = 1; e < E; e++)
            if (logits[e] > v0) { v0 = logits[e]; i0 = e; }
        int i1 = -1; float v1 = -3.0e38f;
        #pragma unroll
        for (int e = 0; e < E; e++)
            if (e != i0 && logits[e] > v1) { v1 = logits[e]; i1 = e; }
        float w0 = 1.f / (1.f + expf(v1 - v0));
        float w1 = 1.f - w0;

        int p0 = atomicAdd(&d_counts[i0], 1);
        d_tok[i0 * NTOK + p0] = n;
        d_wt [i0 * NTOK + p0] = w0;
        d_slot[n * 2 + 0] = i0 * NTOK + p0;

        int p1 = atomicAdd(&d_counts[i1], 1);
        d_tok[i1 * NTOK + p1] = n;
        d_wt [i1 * NTOK + p1] = w1;
        d_slot[n * 2 + 1] = i1 * NTOK + p1;
    }
}

__global__ void scan_kernel() {
    if (threadIdx.x == 0) {
        int t = 0;
        #pragma unroll
        for (int e = 0; e < E; e++) { d_offs[e] = t; t += d_counts[e]; }
    }
}

// ---------------- HMMA grouped GEMM ----------------
// Block tile 128x128x32, 8 warps (2m x 4n), warp tile 64x32.
// fp16 two-term compensation: A = Ah + Al (fp16 pair, 22-bit), B = Bh (fp16).
// acc += Ah*Bh + Al*Bh. Single-stage static SMEM (30KB) -> 2 CTAs/SM.
#define SROW 40

template <bool FIRST>
__global__ void __launch_bounds__(256, 2)
gemm_hmma(const float* __restrict__ x, const float* __restrict__ W,
          const float* __restrict__ bias) {
    const int e = blockIdx.z;
    const int C = d_counts[e];
    const int m0 = blockIdx.y * 128;
    if (m0 >= C) return;
    const int n0 = blockIdx.x * 128;
    constexpr int K = FIRST ? D : H;
    constexpr int NOUT = FIRST ? H : O;
    const int base = d_offs[e];

    __shared__ __align__(16) __half sAh[128][SROW];
    __shared__ __align__(16) __half sAl[128][SROW];
    __shared__ __align__(16) __half sBh[128][SROW];

    const int tid = threadIdx.x;
    const int lane = tid & 31;
    const int wid = tid >> 5;
    const int warp_m = wid >> 2;     // 0..1
    const int warp_n = wid & 3;      // 0..3

    // A staging: row lr, k-half hf (16 of 32)
    const int lr = tid >> 1;
    const int hf = tid & 1;
    // B staging: k-quad kq (k=kq*4), n-quad nq (n=nq*4)
    const int kq = tid & 7;
    const int nq = tid >> 3;         // 0..31

    int mi = m0 + lr; if (mi > C - 1) mi = C - 1;
    const float* arow = FIRST ? (x + (size_t)d_tok[e * NTOK + mi] * D)
                              : (d_h + (size_t)(base + mi) * H);
    const float* wbase = W + (size_t)e * K * NOUT + (size_t)(kq * 4) * NOUT + n0 + nq * 4;

    float acc[4][4][4] = {};

    auto stage = [&](int kb) {
        {
            const float* s = arow + kb + hf * 16;
            float4 f0 = *(const float4*)(s);
            float4 f1 = *(const float4*)(s + 4);
            float4 f2 = *(const float4*)(s + 8);
            float4 f3 = *(const float4*)(s + 12);
            uint32_t h[8], l[8];
            split2h(f0.x, f0.y, h[0], l[0]); split2h(f0.z, f0.w, h[1], l[1]);
            split2h(f1.x, f1.y, h[2], l[2]); split2h(f1.z, f1.w, h[3], l[3]);
            split2h(f2.x, f2.y, h[4], l[4]); split2h(f2.z, f2.w, h[5], l[5]);
            split2h(f3.x, f3.y, h[6], l[6]); split2h(f3.z, f3.w, h[7], l[7]);
            *(uint4*)&sAh[lr][hf * 16]     = make_uint4(h[0], h[1], h[2], h[3]);
            *(uint4*)&sAh[lr][hf * 16 + 8] = make_uint4(h[4], h[5], h[6], h[7]);
            *(uint4*)&sAl[lr][hf * 16]     = make_uint4(l[0], l[1], l[2], l[3]);
            *(uint4*)&sAl[lr][hf * 16 + 8] = make_uint4(l[4], l[5], l[6], l[7]);
        }
        {
            const float* wp = wbase + (size_t)kb * NOUT;
            float4 r0 = *(const float4*)(wp);
            float4 r1 = *(const float4*)(wp + (size_t)NOUT);
            float4 r2 = *(const float4*)(wp + (size_t)2 * NOUT);
            float4 r3 = *(const float4*)(wp + (size_t)3 * NOUT);
            float v[4][4] = {
                {r0.x, r0.y, r0.z, r0.w},
                {r1.x, r1.y, r1.z, r1.w},
                {r2.x, r2.y, r2.z, r2.w},
                {r3.x, r3.y, r3.z, r3.w}};
            #pragma unroll
            for (int j = 0; j < 4; j++) {   // n within quad; pack k-pairs
                uint32_t h0 = pack2h(v[0][j], v[1][j]);
                uint32_t h1 = pack2h(v[2][j], v[3][j]);
                *(uint2*)&sBh[nq * 4 + j][kq * 4] = make_uint2(h0, h1);
            }
        }
    };

    // ldmatrix addressing
    const uint32_t sb_Ah = smem_u32(&sAh[0][0]);
    const uint32_t sb_Al = smem_u32(&sAl[0][0]);
    const uint32_t sb_Bh = smem_u32(&sBh[0][0]);
    const uint32_t a_lane_off = (uint32_t)((lane & 15) * (SROW * 2) + (lane >> 4) * 16)
                              + (uint32_t)(warp_m * 64 * SROW * 2);
    const uint32_t b_lane_off = (uint32_t)(((lane & 7) + (lane >> 4) * 8) * (SROW * 2)
                                           + ((lane >> 3) & 1) * 16)
                              + (uint32_t)(warp_n * 32 * SROW * 2);

    auto compute = [&]() {
        #pragma unroll
        for (int kh = 0; kh < 2; kh++) {
            const uint32_t kb = kh * 32;
            uint32_t bh[2][4];
            uint32_t ah[4][4], al[4][4];
            #pragma unroll
            for (int p = 0; p < 2; p++)
                ldm_x4(bh[p], sb_Bh + b_lane_off + kb + (uint32_t)(p * 16 * SROW * 2));
            #pragma unroll
            for (int mt = 0; mt < 4; mt++) {
                ldm_x4(ah[mt], sb_Ah + a_lane_off + kb + (uint32_t)(mt * 16 * SROW * 2));
                ldm_x4(al[mt], sb_Al + a_lane_off + kb + (uint32_t)(mt * 16 * SROW * 2));
            }
            #pragma unroll
            for (int mt = 0; mt < 4; mt++)
                #pragma unroll
                for (int nt = 0; nt < 4; nt++)
                    mma16816(acc[mt][nt], ah[mt], &bh[nt >> 1][(nt & 1) * 2]);
            #pragma unroll
            for (int mt = 0; mt < 4; mt++)
                #pragma unroll
                for (int nt = 0; nt < 4; nt++)
                    mma16816(acc[mt][nt], al[mt], &bh[nt >> 1][(nt & 1) * 2]);
        }
    };

    const int NCH = K / 32;
    for (int c = 0; c < NCH; c++) {
        stage(c * 32);
        __syncthreads();
        compute();
        __syncthreads();
    }

    // ---------------- epilogue ----------------
    const int g = lane >> 2;
    const int t = lane & 3;
    #pragma unroll
    for (int mt = 0; mt < 4; mt++) {
        const int rw = warp_m * 64 + mt * 16 + g;
        #pragma unroll
        for (int hrow = 0; hrow < 2; hrow++) {
            const int m = m0 + rw + hrow * 8;
            if (m >= C) continue;
            #pragma unroll
            for (int nt = 0; nt < 4; nt++) {
                const int col = n0 + warp_n * 32 + nt * 8 + 2 * t;
                float v0 = acc[mt][nt][hrow * 2 + 0] + bias[e * NOUT + col];
                float v1 = acc[mt][nt][hrow * 2 + 1] + bias[e * NOUT + col + 1];
                if (FIRST) {
                    float2 o;
                    o.x = fmaxf(v0, 0.f);
                    o.y = fmaxf(v1, 0.f);
                    *(float2*)(d_h + (size_t)(base + m) * H + col) = o;
                } else {
                    float wt = d_wt[e * NTOK + m];
                    float2 o;
                    o.x = wt * v0;
                    o.y = wt * v1;
                    *(float2*)(d_y + (size_t)(base + m) * O + col) = o;
                }
            }
        }
    }
}

// ---------------- combine ----------------
__global__ void combine_kernel(float* __restrict__ out) {
    int idx = blockIdx.x * blockDim.x + threadIdx.x;
    int n = idx / (O / 4);
    int o4 = (idx % (O / 4)) * 4;
    int s0 = d_slot[n * 2 + 0];
    int s1 = d_slot[n * 2 + 1];
    int c0 = d_offs[s0 >> 12] + (s0 & (NTOK - 1));
    int c1 = d_offs[s1 >> 12] + (s1 & (NTOK - 1));
    float4 a = *(const float4*)&d_y[(size_t)c0 * O + o4];
    float4 b = *(const float4*)&d_y[(size_t)c1 * O + o4];
    float4 r;
    r.x = a.x + b.x; r.y = a.y + b.y; r.z = a.z + b.z; r.w = a.w + b.w;
    *(float4*)&out[(size_t)n * O + o4] = r;
}

extern "C" void kernel_launch(void* const* d_in, const int* in_sizes, int n_in,
                              void* d_out, int out_size) {
    const float* x  = (const float*)d_in[0];
    const float* W1 = (const float*)d_in[1];
    const float* b1 = (const float*)d_in[2];
    const float* W2 = (const float*)d_in[3];
    const float* b2 = (const float*)d_in[4];
    const float* Wg = (const float*)d_in[5];
    const float* bg = (const float*)d_in[6];
    float* out = (float*)d_out;

    zero_counts_kernel<<<1, 32>>>();
    gate_kernel<<<NTOK, 256>>>(x, Wg, bg);
    scan_kernel<<<1, 1>>>();

    gemm_hmma<true ><<<dim3(H / 128, NTOK / 128, E), 256>>>(x, W1, b1);
    gemm_hmma<false><<<dim3(O / 128, NTOK / 128, E), 256>>>(nullptr, W2, b2);

    combine_kernel<<<(NTOK * O / 4) / 256, 256>>>(out);
}

// round 11
// speedup vs baseline: 2.0576x; 1.2447x over previous
#include <cuda_runtime.h>
#include <cuda_fp16.h>
#include <stdint.h>
#include <math.h>

#define E 8
#define D 1024
#define H 4096
#define O 1024
#define NTOK 4096

// ---------------- scratch ----------------
__device__ int   d_counts[E];
__device__ int   d_offs[E];
__device__ int   d_tok[E * NTOK];
__device__ float d_wt[E * NTOK];
__device__ int   d_slot[NTOK * 2];
__device__ __half d_h[(size_t)2 * NTOK * H];  // gathered hidden, fp16
__device__ float  d_y[(size_t)2 * NTOK * O];  // gathered output, f32

// ---------------- helpers ----------------
__device__ __forceinline__ uint32_t smem_u32(const void* p) {
    uint32_t a;
    asm("{ .reg .u64 t; cvta.to.shared.u64 t, %1; cvt.u32.u64 %0, t; }" : "=r"(a) : "l"(p));
    return a;
}
__device__ __forceinline__ void ldm_x4(uint32_t* d, uint32_t a) {
    asm volatile("ldmatrix.sync.aligned.m8n8.x4.shared.b16 {%0,%1,%2,%3}, [%4];"
                 : "=r"(d[0]), "=r"(d[1]), "=r"(d[2]), "=r"(d[3]) : "r"(a));
}
// non-volatile: pure register computation, lets ptxas schedule.
__device__ __forceinline__ void mma16816(float* c, const uint32_t* a, const uint32_t* b) {
    asm("mma.sync.aligned.m16n8k16.row.col.f32.f16.f16.f32 "
        "{%0,%1,%2,%3}, {%4,%5,%6,%7}, {%8,%9}, {%0,%1,%2,%3};"
        : "+f"(c[0]), "+f"(c[1]), "+f"(c[2]), "+f"(c[3])
        : "r"(a[0]), "r"(a[1]), "r"(a[2]), "r"(a[3]), "r"(b[0]), "r"(b[1]));
}
__device__ __forceinline__ uint32_t pack2h(float x0, float x1) {
    return ((uint32_t)__half_as_ushort(__float2half_rn(x1)) << 16)
         | __half_as_ushort(__float2half_rn(x0));
}

// ---------------- routing ----------------
__global__ void zero_counts_kernel() {
    if (threadIdx.x < E) d_counts[threadIdx.x] = 0;
}

__global__ void gate_kernel(const float* __restrict__ x,
                            const float* __restrict__ Wg,
                            const float* __restrict__ bg) {
    int n = blockIdx.x;
    int tid = threadIdx.x;
    int w = tid >> 5;
    int lane = tid & 31;
    const float* xr = x + (size_t)n * D;

    float acc = 0.f;
    for (int d = lane; d < D; d += 32)
        acc += xr[d] * Wg[d * E + w];
    #pragma unroll
    for (int off = 16; off; off >>= 1)
        acc += __shfl_down_sync(0xffffffffu, acc, off);

    __shared__ float logits[E];
    if (lane == 0) logits[w] = acc + bg[w];
    __syncthreads();

    if (tid == 0) {
        int i0 = 0; float v0 = logits[0];
        #pragma unroll
        for (int e = 1; e < E; e++)
            if (logits[e] > v0) { v0 = logits[e]; i0 = e; }
        int i1 = -1; float v1 = -3.0e38f;
        #pragma unroll
        for (int e = 0; e < E; e++)
            if (e != i0 && logits[e] > v1) { v1 = logits[e]; i1 = e; }
        float w0 = 1.f / (1.f + expf(v1 - v0));
        float w1 = 1.f - w0;

        int p0 = atomicAdd(&d_counts[i0], 1);
        d_tok[i0 * NTOK + p0] = n;
        d_wt [i0 * NTOK + p0] = w0;
        d_slot[n * 2 + 0] = i0 * NTOK + p0;

        int p1 = atomicAdd(&d_counts[i1], 1);
        d_tok[i1 * NTOK + p1] = n;
        d_wt [i1 * NTOK + p1] = w1;
        d_slot[n * 2 + 1] = i1 * NTOK + p1;
    }
}

__global__ void scan_kernel() {
    if (threadIdx.x == 0) {
        int t = 0;
        #pragma unroll
        for (int e = 0; e < E; e++) { d_offs[e] = t; t += d_counts[e]; }
    }
}

// ---------------- HMMA grouped GEMM ----------------
// Block tile 128x128x32, 8 warps (2m x 4n), warp tile 64x32, plain fp16 MMA.
// Single-stage static SMEM (20KB) -> 2 CTAs/SM.
#define SROW 40

template <bool FIRST>
__global__ void __launch_bounds__(256, 2)
gemm_hmma(const float* __restrict__ x, const float* __restrict__ W,
          const float* __restrict__ bias) {
    const int e = blockIdx.z;
    const int C = d_counts[e];
    const int m0 = blockIdx.y * 128;
    if (m0 >= C) return;
    const int n0 = blockIdx.x * 128;
    constexpr int K = FIRST ? D : H;
    constexpr int NOUT = FIRST ? H : O;
    const int base = d_offs[e];

    __shared__ __align__(16) __half sA[128][SROW];
    __shared__ __align__(16) __half sB[128][SROW];

    const int tid = threadIdx.x;
    const int lane = tid & 31;
    const int wid = tid >> 5;
    const int warp_m = wid >> 2;     // 0..1
    const int warp_n = wid & 3;      // 0..3

    // A staging: row lr, k-half hf (16 of 32)
    const int lr = tid >> 1;
    const int hf = tid & 1;
    // B staging: k-quad kq (k=kq*4), n-quad nq (n=nq*4)
    const int kq = tid & 7;
    const int nq = tid >> 3;         // 0..31

    int mi = m0 + lr; if (mi > C - 1) mi = C - 1;
    const float* arow_f = FIRST ? (x + (size_t)d_tok[e * NTOK + mi] * D) : nullptr;
    const __half* arow_h = FIRST ? nullptr : (d_h + (size_t)(base + mi) * H);
    const float* wbase = W + (size_t)e * K * NOUT + (size_t)(kq * 4) * NOUT + n0 + nq * 4;

    float acc[4][4][4] = {};

    auto stage = [&](int kb) {
        if (FIRST) {
            const float* s = arow_f + kb + hf * 16;
            float4 f0 = *(const float4*)(s);
            float4 f1 = *(const float4*)(s + 4);
            float4 f2 = *(const float4*)(s + 8);
            float4 f3 = *(const float4*)(s + 12);
            *(uint4*)&sA[lr][hf * 16] =
                make_uint4(pack2h(f0.x, f0.y), pack2h(f0.z, f0.w),
                           pack2h(f1.x, f1.y), pack2h(f1.z, f1.w));
            *(uint4*)&sA[lr][hf * 16 + 8] =
                make_uint4(pack2h(f2.x, f2.y), pack2h(f2.z, f2.w),
                           pack2h(f3.x, f3.y), pack2h(f3.z, f3.w));
        } else {
            const __half* s = arow_h + kb + hf * 16;
            *(uint4*)&sA[lr][hf * 16]     = *(const uint4*)(s);
            *(uint4*)&sA[lr][hf * 16 + 8] = *(const uint4*)(s + 8);
        }
        {
            const float* wp = wbase + (size_t)kb * NOUT;
            float4 r0 = *(const float4*)(wp);
            float4 r1 = *(const float4*)(wp + (size_t)NOUT);
            float4 r2 = *(const float4*)(wp + (size_t)2 * NOUT);
            float4 r3 = *(const float4*)(wp + (size_t)3 * NOUT);
            float v[4][4] = {
                {r0.x, r0.y, r0.z, r0.w},
                {r1.x, r1.y, r1.z, r1.w},
                {r2.x, r2.y, r2.z, r2.w},
                {r3.x, r3.y, r3.z, r3.w}};
            #pragma unroll
            for (int j = 0; j < 4; j++) {   // n within quad; pack k-pairs
                uint32_t h0 = pack2h(v[0][j], v[1][j]);
                uint32_t h1 = pack2h(v[2][j], v[3][j]);
                *(uint2*)&sB[nq * 4 + j][kq * 4] = make_uint2(h0, h1);
            }
        }
    };

    // ldmatrix addressing
    const uint32_t sb_A = smem_u32(&sA[0][0]);
    const uint32_t sb_B = smem_u32(&sB[0][0]);
    const uint32_t a_lane_off = (uint32_t)((lane & 15) * (SROW * 2) + (lane >> 4) * 16)
                              + (uint32_t)(warp_m * 64 * SROW * 2);
    const uint32_t b_lane_off = (uint32_t)(((lane & 7) + (lane >> 4) * 8) * (SROW * 2)
                                           + ((lane >> 3) & 1) * 16)
                              + (uint32_t)(warp_n * 32 * SROW * 2);

    auto compute = [&]() {
        #pragma unroll
        for (int kh = 0; kh < 2; kh++) {
            const uint32_t kb = kh * 32;
            uint32_t bh[2][4];
            uint32_t ah[4][4];
            #pragma unroll
            for (int p = 0; p < 2; p++)
                ldm_x4(bh[p], sb_B + b_lane_off + kb + (uint32_t)(p * 16 * SROW * 2));
            #pragma unroll
            for (int mt = 0; mt < 4; mt++)
                ldm_x4(ah[mt], sb_A + a_lane_off + kb + (uint32_t)(mt * 16 * SROW * 2));
            #pragma unroll
            for (int mt = 0; mt < 4; mt++)
                #pragma unroll
                for (int nt = 0; nt < 4; nt++)
                    mma16816(acc[mt][nt], ah[mt], &bh[nt >> 1][(nt & 1) * 2]);
        }
    };

    const int NCH = K / 32;
    for (int c = 0; c < NCH; c++) {
        stage(c * 32);
        __syncthreads();
        compute();
        __syncthreads();
    }

    // ---------------- epilogue ----------------
    const int g = lane >> 2;
    const int t = lane & 3;
    #pragma unroll
    for (int mt = 0; mt < 4; mt++) {
        const int rw = warp_m * 64 + mt * 16 + g;
        #pragma unroll
        for (int hrow = 0; hrow < 2; hrow++) {
            const int m = m0 + rw + hrow * 8;
            if (m >= C) continue;
            #pragma unroll
            for (int nt = 0; nt < 4; nt++) {
                const int col = n0 + warp_n * 32 + nt * 8 + 2 * t;
                float v0 = acc[mt][nt][hrow * 2 + 0] + bias[e * NOUT + col];
                float v1 = acc[mt][nt][hrow * 2 + 1] + bias[e * NOUT + col + 1];
                if (FIRST) {
                    uint32_t hp = pack2h(fmaxf(v0, 0.f), fmaxf(v1, 0.f));
                    *(uint32_t*)(d_h + (size_t)(base + m) * H + col) = hp;
                } else {
                    float wt = d_wt[e * NTOK + m];
                    float2 o;
                    o.x = wt * v0;
                    o.y = wt * v1;
                    *(float2*)(d_y + (size_t)(base + m) * O + col) = o;
                }
            }
        }
    }
}

// ---------------- combine ----------------
__global__ void combine_kernel(float* __restrict__ out) {
    int idx = blockIdx.x * blockDim.x + threadIdx.x;
    int n = idx / (O / 4);
    int o4 = (idx % (O / 4)) * 4;
    int s0 = d_slot[n * 2 + 0];
    int s1 = d_slot[n * 2 + 1];
    int c0 = d_offs[s0 >> 12] + (s0 & (NTOK - 1));
    int c1 = d_offs[s1 >> 12] + (s1 & (NTOK - 1));
    float4 a = *(const float4*)&d_y[(size_t)c0 * O + o4];
    float4 b = *(const float4*)&d_y[(size_t)c1 * O + o4];
    float4 r;
    r.x = a.x + b.x; r.y = a.y + b.y; r.z = a.z + b.z; r.w = a.w + b.w;
    *(float4*)&out[(size_t)n * O + o4] = r;
}

extern "C" void kernel_launch(void* const* d_in, const int* in_sizes, int n_in,
                              void* d_out, int out_size) {
    const float* x  = (const float*)d_in[0];
    const float* W1 = (const float*)d_in[1];
    const float* b1 = (const float*)d_in[2];
    const float* W2 = (const float*)d_in[3];
    const float* b2 = (const float*)d_in[4];
    const float* Wg = (const float*)d_in[5];
    const float* bg = (const float*)d_in[6];
    float* out = (float*)d_out;

    zero_counts_kernel<<<1, 32>>>();
    gate_kernel<<<NTOK, 256>>>(x, Wg, bg);
    scan_kernel<<<1, 1>>>();

    gemm_hmma<true ><<<dim3(H / 128, NTOK / 128, E), 256>>>(x, W1, b1);
    gemm_hmma<false><<<dim3(O / 128, NTOK / 128, E), 256>>>(nullptr, W2, b2);

    combine_kernel<<<(NTOK * O / 4) / 256, 256>>>(out);
}

// round 13
// speedup vs baseline: 3.6269x; 1.7627x over previous
#include <cuda_runtime.h>
#include <cuda_fp16.h>
#include <stdint.h>
#include <math.h>

#define E 8
#define D 1024
#define H 4096
#define O 1024
#define NTOK 4096

// ---------------- scratch ----------------
__device__ int    d_counts[E];
__device__ int    d_offs[E];
__device__ int    d_tok[E * NTOK];
__device__ float  d_wt[E * NTOK];
__device__ int    d_slot[NTOK * 2];
__device__ __half d_xh[(size_t)NTOK * D];       // x in fp16
__device__ __half d_h[(size_t)2 * NTOK * H];    // gathered hidden, fp16
__device__ float  d_y[(size_t)2 * NTOK * O];    // gathered output, f32
__device__ __half d_w1t[(size_t)E * H * D];     // W1^T fp16 [E,H,D]
__device__ __half d_w2t[(size_t)E * O * H];     // W2^T fp16 [E,O,H]

// ---------------- helpers ----------------
__device__ __forceinline__ uint32_t smem_u32(const void* p) {
    uint32_t a;
    asm("{ .reg .u64 t; cvta.to.shared.u64 t, %1; cvt.u32.u64 %0, t; }" : "=r"(a) : "l"(p));
    return a;
}
__device__ __forceinline__ void ldm_x4(uint32_t* d, uint32_t a) {
    asm volatile("ldmatrix.sync.aligned.m8n8.x4.shared.b16 {%0,%1,%2,%3}, [%4];"
                 : "=r"(d[0]), "=r"(d[1]), "=r"(d[2]), "=r"(d[3]) : "r"(a));
}
__device__ __forceinline__ void mma16816(float* c, const uint32_t* a, const uint32_t* b) {
    asm("mma.sync.aligned.m16n8k16.row.col.f32.f16.f16.f32 "
        "{%0,%1,%2,%3}, {%4,%5,%6,%7}, {%8,%9}, {%0,%1,%2,%3};"
        : "+f"(c[0]), "+f"(c[1]), "+f"(c[2]), "+f"(c[3])
        : "r"(a[0]), "r"(a[1]), "r"(a[2]), "r"(a[3]), "r"(b[0]), "r"(b[1]));
}
__device__ __forceinline__ uint32_t pack2h(float x0, float x1) {
    return ((uint32_t)__half_as_ushort(__float2half_rn(x1)) << 16)
         | __half_as_ushort(__float2half_rn(x0));
}
__device__ __forceinline__ void cp16(uint32_t dst, const void* src) {
    asm volatile("cp.async.cg.shared.global [%0], [%1], 16;" :: "r"(dst), "l"(src));
}
__device__ __forceinline__ void cp_commit() {
    asm volatile("cp.async.commit_group;" ::: "memory");
}
template <int N>
__device__ __forceinline__ void cp_wait() {
    asm volatile("cp.async.wait_group %0;" :: "n"(N) : "memory");
}

// ---------------- routing ----------------
__global__ void zero_counts_kernel() {
    if (threadIdx.x < E) d_counts[threadIdx.x] = 0;
}

__global__ void gate_kernel(const float* __restrict__ x,
                            const float* __restrict__ Wg,
                            const float* __restrict__ bg) {
    int n = blockIdx.x;
    int tid = threadIdx.x;
    int w = tid >> 5;
    int lane = tid & 31;
    const float* xr = x + (size_t)n * D;

    float acc = 0.f;
    for (int d = lane; d < D; d += 32)
        acc += xr[d] * Wg[d * E + w];
    #pragma unroll
    for (int off = 16; off; off >>= 1)
        acc += __shfl_down_sync(0xffffffffu, acc, off);

    __shared__ float logits[E];
    if (lane == 0) logits[w] = acc + bg[w];
    __syncthreads();

    if (tid == 0) {
        int i0 = 0; float v0 = logits[0];
        #pragma unroll
        for (int e = 1; e < E; e++)
            if (logits[e] > v0) { v0 = logits[e]; i0 = e; }
        int i1 = -1; float v1 = -3.0e38f;
        #pragma unroll
        for (int e = 0; e < E; e++)
            if (e != i0 && logits[e] > v1) { v1 = logits[e]; i1 = e; }
        float w0 = 1.f / (1.f + expf(v1 - v0));
        float w1 = 1.f - w0;

        int p0 = atomicAdd(&d_counts[i0], 1);
        d_tok[i0 * NTOK + p0] = n;
        d_wt [i0 * NTOK + p0] = w0;
        d_slot[n * 2 + 0] = i0 * NTOK + p0;

        int p1 = atomicAdd(&d_counts[i1], 1);
        d_tok[i1 * NTOK + p1] = n;
        d_wt [i1 * NTOK + p1] = w1;
        d_slot[n * 2 + 1] = i1 * NTOK + p1;
    }
}

__global__ void scan_kernel() {
    if (threadIdx.x == 0) {
        int t = 0;
        #pragma unroll
        for (int e = 0; e < E; e++) { d_offs[e] = t; t += d_counts[e]; }
    }
}

// ---------------- prep: x -> fp16 (device symbol written in-kernel) ----------------
__global__ void conv_x_kernel(const float* __restrict__ x) {
    int i = blockIdx.x * blockDim.x + threadIdx.x;   // over N*D/2
    float2 v = ((const float2*)x)[i];
    ((uint32_t*)d_xh)[i] = pack2h(v.x, v.y);
}

// ---------------- prep: W [E][K][NOUT] f32 -> WT [E][NOUT][K] fp16 ----------------
// IMPORTANT: output scratch referenced as device symbol INSIDE the kernel
// (host-passed __device__ symbol pointers are invalid -> R3/R12 zero-weight bug).
template <bool FIRST>
__global__ void transpose_h_kernel(const float* __restrict__ in) {
    constexpr int Kd = FIRST ? D : H;
    constexpr int Nd = FIRST ? H : O;
    __half* out = FIRST ? d_w1t : d_w2t;
    __shared__ float t[32][33];
    int e = blockIdx.z;
    int n0 = blockIdx.x * 32, k0 = blockIdx.y * 32;
    int tx = threadIdx.x, ty = threadIdx.y;
    const float* ie = in + (size_t)e * Kd * Nd;
    #pragma unroll
    for (int i = 0; i < 32; i += 8)
        t[ty + i][tx] = ie[(size_t)(k0 + ty + i) * Nd + n0 + tx];
    __syncthreads();
    __half* oe = out + (size_t)e * Nd * Kd;
    #pragma unroll
    for (int i = 0; i < 32; i += 8)
        oe[(size_t)(n0 + ty + i) * Kd + k0 + tx] = __float2half_rn(t[tx][ty + i]);
}

// ---------------- HMMA grouped GEMM, cp.async 3-stage ----------------
// Block tile 128x128x32, 8 warps (2m x 4n), warp tile 64x32, plain fp16 MMA.
// All operands fp16 row-major in global; staging = pure cp.async.cg copies.
#define SROW 40
#define TILE_BYTES (128 * SROW * 2)        // 10240
#define STAGE_BYTES (2 * TILE_BYTES)       // A|B = 20480
#define NSTAGE 3

template <bool FIRST>
__global__ void __launch_bounds__(256, 2)
gemm_hmma(const float* __restrict__ bias) {
    const int e = blockIdx.z;
    const int C = d_counts[e];
    const int m0 = blockIdx.y * 128;
    if (m0 >= C) return;
    const int n0 = blockIdx.x * 128;
    constexpr int K = FIRST ? D : H;
    constexpr int NOUT = FIRST ? H : O;
    const int base = d_offs[e];

    extern __shared__ __align__(16) char smem[];
    const uint32_t sb = smem_u32(smem);

    const int tid = threadIdx.x;
    const int lane = tid & 31;
    const int wid = tid >> 5;
    const int warp_m = wid >> 2;     // 0..1
    const int warp_n = wid & 3;      // 0..3

    // staging: thread owns row lr (both A and B), 32B part hf
    const int lr = tid >> 1;
    const int hf = tid & 1;

    int mi = m0 + lr; if (mi > C - 1) mi = C - 1;
    const __half* arow = FIRST ? (d_xh + (size_t)d_tok[e * NTOK + mi] * D)
                               : (d_h + (size_t)(base + mi) * H);
    const __half* brow = (FIRST ? d_w1t : d_w2t) + ((size_t)e * NOUT + n0 + lr) * K;

    float acc[4][4][4] = {};

    auto issue = [&](int slot, int kb) {
        uint32_t dA = sb + (uint32_t)(slot * STAGE_BYTES) + (uint32_t)(lr * 80 + hf * 32);
        const __half* sa = arow + kb + hf * 16;
        cp16(dA, sa);
        cp16(dA + 16, sa + 8);
        uint32_t dB = dA + (uint32_t)TILE_BYTES;
        const __half* sbp = brow + kb + hf * 16;
        cp16(dB, sbp);
        cp16(dB + 16, sbp + 8);
    };

    // ldmatrix addressing (validated layout, 80B pitch)
    const uint32_t a_lane_off = (uint32_t)((lane & 15) * (SROW * 2) + (lane >> 4) * 16)
                              + (uint32_t)(warp_m * 64 * SROW * 2);
    const uint32_t b_lane_off = (uint32_t)(((lane & 7) + (lane >> 4) * 8) * (SROW * 2)
                                           + ((lane >> 3) & 1) * 16)
                              + (uint32_t)(warp_n * 32 * SROW * 2);

    auto compute = [&](int slot) {
        const uint32_t sA = sb + (uint32_t)(slot * STAGE_BYTES);
        const uint32_t sB = sA + (uint32_t)TILE_BYTES;
        #pragma unroll
        for (int kh = 0; kh < 2; kh++) {
            const uint32_t kb = kh * 32;
            uint32_t bh[2][4];
            uint32_t ah[4][4];
            #pragma unroll
            for (int p = 0; p < 2; p++)
                ldm_x4(bh[p], sB + b_lane_off + kb + (uint32_t)(p * 16 * SROW * 2));
            #pragma unroll
            for (int mt = 0; mt < 4; mt++)
                ldm_x4(ah[mt], sA + a_lane_off + kb + (uint32_t)(mt * 16 * SROW * 2));
            #pragma unroll
            for (int mt = 0; mt < 4; mt++)
                #pragma unroll
                for (int nt = 0; nt < 4; nt++)
                    mma16816(acc[mt][nt], ah[mt], &bh[nt >> 1][(nt & 1) * 2]);
        }
    };

    const int NCH = K / 32;
    issue(0, 0);  cp_commit();
    issue(1, 32); cp_commit();
    for (int c = 0; c < NCH; c++) {
        cp_wait<1>();            // chunk c complete
        __syncthreads();         // visible to all; prior compute on reused slot done
        if (c + 2 < NCH) issue((c + 2) % NSTAGE, (c + 2) * 32);
        cp_commit();
        compute(c % NSTAGE);
    }

    // ---------------- epilogue ----------------
    const int g = lane >> 2;
    const int t = lane & 3;
    #pragma unroll
    for (int mt = 0; mt < 4; mt++) {
        const int rw = warp_m * 64 + mt * 16 + g;
        #pragma unroll
        for (int hrow = 0; hrow < 2; hrow++) {
            const int m = m0 + rw + hrow * 8;
            if (m >= C) continue;
            #pragma unroll
            for (int nt = 0; nt < 4; nt++) {
                const int col = n0 + warp_n * 32 + nt * 8 + 2 * t;
                float v0 = acc[mt][nt][hrow * 2 + 0] + bias[e * NOUT + col];
                float v1 = acc[mt][nt][hrow * 2 + 1] + bias[e * NOUT + col + 1];
                if (FIRST) {
                    uint32_t hp = pack2h(fmaxf(v0, 0.f), fmaxf(v1, 0.f));
                    *(uint32_t*)(d_h + (size_t)(base + m) * H + col) = hp;
                } else {
                    float wt = d_wt[e * NTOK + m];
                    float2 o;
                    o.x = wt * v0;
                    o.y = wt * v1;
                    *(float2*)(d_y + (size_t)(base + m) * O + col) = o;
                }
            }
        }
    }
}

// ---------------- combine ----------------
__global__ void combine_kernel(float* __restrict__ out) {
    int idx = blockIdx.x * blockDim.x + threadIdx.x;
    int n = idx / (O / 4);
    int o4 = (idx % (O / 4)) * 4;
    int s0 = d_slot[n * 2 + 0];
    int s1 = d_slot[n * 2 + 1];
    int c0 = d_offs[s0 >> 12] + (s0 & (NTOK - 1));
    int c1 = d_offs[s1 >> 12] + (s1 & (NTOK - 1));
    float4 a = *(const float4*)&d_y[(size_t)c0 * O + o4];
    float4 b = *(const float4*)&d_y[(size_t)c1 * O + o4];
    float4 r;
    r.x = a.x + b.x; r.y = a.y + b.y; r.z = a.z + b.z; r.w = a.w + b.w;
    *(float4*)&out[(size_t)n * O + o4] = r;
}

extern "C" void kernel_launch(void* const* d_in, const int* in_sizes, int n_in,
                              void* d_out, int out_size) {
    const float* x  = (const float*)d_in[0];
    const float* W1 = (const float*)d_in[1];
    const float* b1 = (const float*)d_in[2];
    const float* W2 = (const float*)d_in[3];
    const float* b2 = (const float*)d_in[4];
    const float* Wg = (const float*)d_in[5];
    const float* bg = (const float*)d_in[6];
    float* out = (float*)d_out;

    cudaFuncSetAttribute(gemm_hmma<true>,  cudaFuncAttributeMaxDynamicSharedMemorySize, NSTAGE * STAGE_BYTES);
    cudaFuncSetAttribute(gemm_hmma<false>, cudaFuncAttributeMaxDynamicSharedMemorySize, NSTAGE * STAGE_BYTES);

    zero_counts_kernel<<<1, 32>>>();
    gate_kernel<<<NTOK, 256>>>(x, Wg, bg);
    scan_kernel<<<1, 1>>>();

    conv_x_kernel<<<(NTOK * D / 2) / 256, 256>>>(x);
    transpose_h_kernel<true ><<<dim3(H / 32, D / 32, E), dim3(32, 8)>>>(W1);
    transpose_h_kernel<false><<<dim3(O / 32, H / 32, E), dim3(32, 8)>>>(W2);

    gemm_hmma<true ><<<dim3(H / 128, NTOK / 128, E), 256, NSTAGE * STAGE_BYTES>>>(b1);
    gemm_hmma<false><<<dim3(O / 128, NTOK / 128, E), 256, NSTAGE * STAGE_BYTES>>>(b2);

    combine_kernel<<<(NTOK * O / 4) / 256, 256>>>(out);
}